// round 7
// baseline (speedup 1.0000x reference)
#include <cuda_runtime.h>

typedef unsigned long long u64;

#define DN 50000
#define DE 800000
#define DK 40000
#define NBLK 49   // ceil(DN/1024) for the kept-node compaction

// ---------------- scratch layout (single __device__ blob) ----------------
static constexpr size_t OFF_XW   = 0;                               // DN*128 gemm out (scaled)
static constexpr size_t OFF_HA   = OFF_XW  + (size_t)DN*128*4;      // DN*128 gather out
static constexpr size_t OFF_HP   = OFF_HA  + (size_t)DN*128*4;      // DK*128 pooled feats
static constexpr size_t OFF_GM   = OFF_HP  + (size_t)DK*128*4;      // DK*64 gemm out (scaled)
static constexpr size_t OFF_T2   = OFF_GM  + (size_t)DK*64*4;       // DK*64 gather out
static constexpr size_t OFF_DIS1 = OFF_T2  + (size_t)DK*64*4;       // DN
static constexpr size_t OFF_DIS2 = OFF_DIS1 + (size_t)DN*4;         // DK
static constexpr size_t OFF_DEG1 = OFF_DIS2 + (size_t)DK*4;         // DN
static constexpr size_t OFF_DEG2 = OFF_DEG1 + (size_t)DN*4;         // DK
static constexpr size_t OFF_RP1  = OFF_DEG2 + (size_t)DK*4;         // DN+1
static constexpr size_t OFF_CUR1 = OFF_RP1  + (size_t)(DN+1)*4;     // DN
static constexpr size_t OFF_RP2  = OFF_CUR1 + (size_t)DN*4;         // DK+1
static constexpr size_t OFF_CUR2 = OFF_RP2  + (size_t)(DK+1)*4;     // DK
static constexpr size_t OFF_CSR1 = OFF_CUR2 + (size_t)DK*4;         // DE
static constexpr size_t OFF_CSR2 = OFF_CSR1 + (size_t)DE*4;         // DE
static constexpr size_t OFF_NS   = OFF_CSR2 + (size_t)DE*4;         // DE
static constexpr size_t OFF_ND   = OFF_NS   + (size_t)DE*4;         // DE
static constexpr size_t OFF_SCORE= OFF_ND   + (size_t)DE*4;         // DN
static constexpr size_t OFF_KEY  = OFF_SCORE+ (size_t)DN*4;         // DN u64
static constexpr size_t OFF_CAND = OFF_KEY  + (size_t)DN*8;         // DN u64 (boundary-bin candidates)
static constexpr size_t OFF_NEW  = OFF_CAND + (size_t)DN*8;         // DN
static constexpr size_t OFF_BINS = OFF_NEW  + (size_t)DN*4;
static constexpr size_t OFF_BSUM = OFF_BINS + 256*4;                // 64
static constexpr size_t OFF_BOFF = OFF_BSUM + 64*4;                 // 64
static constexpr size_t OFF_PFX  = OFF_BOFF + 64*4;
static constexpr size_t OFF_REM  = OFF_PFX  + 8;
static constexpr size_t OFF_WN   = OFF_REM  + 4;
static constexpr size_t OFF_CCNT = OFF_WN   + 4;
static constexpr size_t OFF_SYNC = OFF_CCNT + 4;                    // 4 ints: ctr1,flag1,ctr2,flag2
static constexpr size_t OFF_ACC  = OFF_SYNC + 4*4;
static constexpr size_t TOTAL_BYTES = OFF_ACC + 64*4;

__device__ __align__(256) unsigned char g_scratch[TOTAL_BYTES];

// ---------------- init: reset all per-replay state in one launch ------------
__global__ void init_kernel(int* deg1, int* deg2, int* bins, float* acc,
                            int* rem, u64* pfx, int* ccnt, int* sync){
    int i = blockIdx.x*blockDim.x + threadIdx.x;
    if (i < DN)  deg1[i] = 0;
    if (i < DK)  deg2[i] = 0;
    if (i < 256) bins[i] = 0;
    if (i < 64)  acc[i]  = 0.f;
    if (i < 4)   sync[i] = 0;
    if (i == 0){ *rem = DK; *pfx = 0ull; *ccnt = 0; }
}

// ---------------- GEMM 8x8 register tile, transposed sX (conflict-free) -----
// Y[r][c] = dis[r] * sum_k X[r][k]*W[k][c];  THREADS = (ROWS/8)*(KOUT/8) = 128
template<int KIN, int KOUT, int ROWS>
__global__ __launch_bounds__(128) void gemm8t(const float* __restrict__ X,
                                              const float* __restrict__ W,
                                              const float* __restrict__ dis,
                                              float* __restrict__ Y, int M){
    constexpr int CG = KOUT/8;           // col groups of 8
    constexpr int THREADS = 128;
    extern __shared__ float sm[];
    float* sW = sm;                      // KIN*KOUT, row-major (k-major rows)
    float* sX = sm + KIN*KOUT;           // TRANSPOSED: sX[k*ROWS + r]
    const int tid = threadIdx.x;
    for (int i = tid; i < KIN*KOUT/4; i += THREADS)
        ((float4*)sW)[i] = ((const float4*)W)[i];
    const int row0 = blockIdx.x * ROWS;
    for (int i = tid; i < ROWS*(KIN/4); i += THREADS){
        int r  = i / (KIN/4);
        int c4 = i % (KIN/4);
        int gr = row0 + r;
        float4 v = (gr < M) ? ((const float4*)X)[(size_t)gr*(KIN/4) + c4]
                            : make_float4(0.f,0.f,0.f,0.f);
        sX[(4*c4+0)*ROWS + r] = v.x;
        sX[(4*c4+1)*ROWS + r] = v.y;
        sX[(4*c4+2)*ROWS + r] = v.z;
        sX[(4*c4+3)*ROWS + r] = v.w;
    }
    __syncthreads();
    const int tx = tid % CG;             // col group
    const int ty = tid / CG;             // row group
    const int r0 = ty*8;
    const int c4 = tx*2;                 // two float4 per 8 cols
    const float4* w4 = (const float4*)sW;
    float4 a0[8], a1[8];
    #pragma unroll
    for (int i = 0; i < 8; i++){ a0[i] = make_float4(0,0,0,0); a1[i] = a0[i]; }
    #pragma unroll 4
    for (int k = 0; k < KIN; k++){
        float4 w0 = w4[k*(KOUT/4) + c4];
        float4 w1 = w4[k*(KOUT/4) + c4 + 1];
        float4 x03 = *(const float4*)&sX[k*ROWS + r0];
        float4 x47 = *(const float4*)&sX[k*ROWS + r0 + 4];
        float xv[8] = {x03.x, x03.y, x03.z, x03.w, x47.x, x47.y, x47.z, x47.w};
        #pragma unroll
        for (int i = 0; i < 8; i++){
            a0[i].x += xv[i]*w0.x; a0[i].y += xv[i]*w0.y;
            a0[i].z += xv[i]*w0.z; a0[i].w += xv[i]*w0.w;
            a1[i].x += xv[i]*w1.x; a1[i].y += xv[i]*w1.y;
            a1[i].z += xv[i]*w1.z; a1[i].w += xv[i]*w1.w;
        }
    }
    float4* yp = (float4*)Y;
    #pragma unroll
    for (int i = 0; i < 8; i++){
        int gr = row0 + r0 + i;
        if (gr < M){
            float s = dis[gr];
            float4 v0 = a0[i], v1 = a1[i];
            v0.x*=s; v0.y*=s; v0.z*=s; v0.w*=s;
            v1.x*=s; v1.y*=s; v1.z*=s; v1.w*=s;
            yp[(size_t)gr*(KOUT/4) + c4]     = v0;
            yp[(size_t)gr*(KOUT/4) + c4 + 1] = v1;
        }
    }
}

// ---------------- degree histogram ----------------
__global__ void deg_kernel(const int* __restrict__ dst, int* __restrict__ deg){
    int e = blockIdx.x*blockDim.x + threadIdx.x;
    if (e < DE) atomicAdd(&deg[dst[e]], 1);
}

// ---------------- fused single-wave scan: deg -> rowptr/cur/dis -------------
// nb <= 64 blocks, all co-resident (<=148 SMs). Last-arriving block scans partials.
__global__ void fused_scan_kernel(const int* __restrict__ deg,
                                  int* __restrict__ bsums, int* __restrict__ boff,
                                  int* __restrict__ ctr, int* __restrict__ flag,
                                  int* __restrict__ rowptr, int* __restrict__ cur,
                                  float* __restrict__ dis, int M, int nb){
    __shared__ int sh[1024];
    const int tid = threadIdx.x;
    const int b = blockIdx.x;
    const int i = b*1024 + tid;
    int v = (i < M) ? deg[i] : 0;
    sh[tid] = v;
    __syncthreads();
    #pragma unroll
    for (int o = 1; o < 1024; o <<= 1){
        int t = (tid >= o) ? sh[tid - o] : 0;
        __syncthreads();
        sh[tid] += t;
        __syncthreads();
    }
    if (tid == 0){
        bsums[b] = sh[1023];
        __threadfence();
        int old = atomicAdd(ctr, 1);
        if (old == nb - 1){
            int a = 0;
            for (int j = 0; j < nb; j++){ int t = bsums[j]; boff[j] = a; a += t; }
            __threadfence();
            atomicExch(flag, 1);
        }
        while (atomicAdd(flag, 0) == 0) {}
    }
    __syncthreads();
    if (i < M){
        int excl = boff[b] + sh[tid] - v;
        rowptr[i] = excl;
        cur[i]    = excl;
        dis[i]    = rsqrtf(1.0f + (float)v);
        if (i == M-1) rowptr[M] = excl + v;
    }
}

// ---------------- CSR scatter ----------------
__global__ void scatter1_kernel(const int* __restrict__ src, const int* __restrict__ dst,
                                int* __restrict__ cur, int* __restrict__ csr){
    int e = blockIdx.x*blockDim.x + threadIdx.x;
    if (e >= DE) return;
    int pos = atomicAdd(&cur[dst[e]], 1);
    csr[pos] = src[e];
}

__global__ void scatter2_kernel(const int* __restrict__ ns, const int* __restrict__ nd,
                                int* __restrict__ cur, int* __restrict__ csr){
    int e = blockIdx.x*blockDim.x + threadIdx.x;
    if (e >= DE) return;
    int a = ns[e];
    if (a < 0) return;
    int pos = atomicAdd(&cur[nd[e]], 1);
    csr[pos] = a;
}

// ---------------- CSR gathers over dis-prescaled features ----------------
template<bool RELU>
__global__ void gather128_kernel(const int* __restrict__ rowptr, const int* __restrict__ csr,
                                 const float* __restrict__ dis, const float* __restrict__ Hs,
                                 const float* __restrict__ bias, float* __restrict__ Hout, int M){
    int w = (blockIdx.x*blockDim.x + threadIdx.x) >> 5;
    int lane = threadIdx.x & 31;
    if (w >= M) return;
    int beg = rowptr[w], end = rowptr[w+1];
    float dn = dis[w];
    const float4* H4 = (const float4*)Hs;
    float4 acc = H4[(size_t)w*32 + lane];     // self (scaled) term
    for (int j = beg; j < end; j += 32){
        int e = j + lane;
        int myi = (e < end) ? csr[e] : 0;
        int cnt = min(32, end - j);
        for (int t = 0; t < cnt; t++){
            int s = __shfl_sync(0xffffffffu, myi, t);
            float4 v = H4[(size_t)s*32 + lane];
            acc.x += v.x; acc.y += v.y; acc.z += v.z; acc.w += v.w;
        }
    }
    float4 b = ((const float4*)bias)[lane];
    acc.x = acc.x*dn + b.x; acc.y = acc.y*dn + b.y;
    acc.z = acc.z*dn + b.z; acc.w = acc.w*dn + b.w;
    if (RELU){
        acc.x = fmaxf(acc.x, 0.f); acc.y = fmaxf(acc.y, 0.f);
        acc.z = fmaxf(acc.z, 0.f); acc.w = fmaxf(acc.w, 0.f);
    }
    ((float4*)Hout)[(size_t)w*32 + lane] = acc;
}

// DIM=64: half-warp per node (16 lanes x float4)
template<bool RELU>
__global__ void gather64_kernel(const int* __restrict__ rowptr, const int* __restrict__ csr,
                                const float* __restrict__ dis, const float* __restrict__ Hs,
                                const float* __restrict__ bias, float* __restrict__ Hout, int M){
    int gw = (blockIdx.x*blockDim.x + threadIdx.x) >> 5;
    int lane = threadIdx.x & 31;
    int half = lane >> 4;
    int sub  = lane & 15;
    int n = gw*2 + half;
    if (n >= M) return;   // M even -> warp-uniform exit
    int beg = rowptr[n], end = rowptr[n+1];
    float dn = dis[n];
    const float4* H4 = (const float4*)Hs;
    float4 acc = H4[(size_t)n*16 + sub];
    unsigned mask = 0xFFFFu << (half*16);
    for (int j = beg; j < end; j += 16){
        int e = j + sub;
        int myi = (e < end) ? csr[e] : 0;
        int cnt = min(16, end - j);
        for (int t = 0; t < cnt; t++){
            int s = __shfl_sync(mask, myi, t, 16);
            float4 v = H4[(size_t)s*16 + sub];
            acc.x += v.x; acc.y += v.y; acc.z += v.z; acc.w += v.w;
        }
    }
    float4 b = ((const float4*)bias)[sub];
    acc.x = acc.x*dn + b.x; acc.y = acc.y*dn + b.y;
    acc.z = acc.z*dn + b.z; acc.w = acc.w*dn + b.w;
    if (RELU){
        acc.x = fmaxf(acc.x, 0.f); acc.y = fmaxf(acc.y, 0.f);
        acc.z = fmaxf(acc.z, 0.f); acc.w = fmaxf(acc.w, 0.f);
    }
    ((float4*)Hout)[(size_t)n*16 + sub] = acc;
}

// conv4: gather + global mean accumulation (bias added at writeout)
__global__ void gather64_reduce_kernel(const int* __restrict__ rowptr, const int* __restrict__ csr,
                                       const float* __restrict__ dis, const float* __restrict__ Hs,
                                       float* __restrict__ accOut){
    __shared__ float sh[64];
    const int lane = threadIdx.x & 31;
    const int half = lane >> 4;
    const int sub  = lane & 15;
    const int wloc = threadIdx.x >> 5;
    const int wpb  = blockDim.x >> 5;
    if (threadIdx.x < 64) sh[threadIdx.x] = 0.f;
    __syncthreads();
    int gw = blockIdx.x*wpb + wloc;
    int tw = gridDim.x*wpb;
    const float4* H4 = (const float4*)Hs;
    unsigned mask = 0xFFFFu << (half*16);
    float4 sum = make_float4(0,0,0,0);
    for (int n = gw*2 + half; n < DK; n += tw*2){
        int beg = rowptr[n], end = rowptr[n+1];
        float dn = dis[n];
        float4 a = H4[(size_t)n*16 + sub];
        for (int j = beg; j < end; j += 16){
            int e = j + sub;
            int myi = (e < end) ? csr[e] : 0;
            int cnt = min(16, end - j);
            for (int t = 0; t < cnt; t++){
                int s = __shfl_sync(mask, myi, t, 16);
                float4 v = H4[(size_t)s*16 + sub];
                a.x += v.x; a.y += v.y; a.z += v.z; a.w += v.w;
            }
        }
        sum.x += a.x*dn; sum.y += a.y*dn; sum.z += a.z*dn; sum.w += a.w*dn;
    }
    sum.x += __shfl_xor_sync(0xffffffffu, sum.x, 16);
    sum.y += __shfl_xor_sync(0xffffffffu, sum.y, 16);
    sum.z += __shfl_xor_sync(0xffffffffu, sum.z, 16);
    sum.w += __shfl_xor_sync(0xffffffffu, sum.w, 16);
    if (half == 0){
        atomicAdd(&sh[sub*4+0], sum.x);
        atomicAdd(&sh[sub*4+1], sum.y);
        atomicAdd(&sh[sub*4+2], sum.z);
        atomicAdd(&sh[sub*4+3], sum.w);
    }
    __syncthreads();
    if (threadIdx.x < 64) atomicAdd(&accOut[threadIdx.x], sh[threadIdx.x]);
}

__global__ void write_out_kernel(const float* __restrict__ acc, const float* __restrict__ b4,
                                 float* __restrict__ out){
    if (threadIdx.x < 64)
        out[threadIdx.x] = acc[threadIdx.x] * (1.0f/(float)DK) + b4[threadIdx.x];
}

// ---------------- pooling: score + exact top-K radix select ----------------
__global__ void wnorm_kernel(const float* __restrict__ w, float* wn){
    float v = w[threadIdx.x]; v *= v;
    #pragma unroll
    for (int o = 16; o; o >>= 1) v += __shfl_xor_sync(0xffffffffu, v, o);
    __shared__ float sh[4];
    if ((threadIdx.x & 31) == 0) sh[threadIdx.x >> 5] = v;
    __syncthreads();
    if (threadIdx.x == 0) *wn = sqrtf(sh[0]+sh[1]+sh[2]+sh[3]);
}

__global__ void score_kernel(const float* __restrict__ H, const float* __restrict__ w,
                             const float* __restrict__ wn,
                             float* __restrict__ score, u64* __restrict__ key){
    int t = blockIdx.x*blockDim.x + threadIdx.x;
    int n = t >> 5, lane = t & 31;
    if (n >= DN) return;
    float4 a = ((const float4*)H)[(size_t)n*32 + lane];
    float4 b = ((const float4*)w)[lane];
    float s = a.x*b.x + a.y*b.y + a.z*b.z + a.w*b.w;
    #pragma unroll
    for (int o = 16; o; o >>= 1) s += __shfl_xor_sync(0xffffffffu, s, o);
    if (lane == 0){
        s = tanhf(s / *wn);
        score[n] = s;
        unsigned ub = __float_as_uint(s);
        ub = (ub & 0x80000000u) ? ~ub : (ub | 0x80000000u);   // order-preserving map
        key[n] = ((u64)ub << 32) | (u64)(0xffffffffu - (unsigned)n);  // distinct keys
    }
}

__global__ void hist_kernel(const u64* __restrict__ key, int* __restrict__ bins){
    __shared__ int sb[256];
    if (threadIdx.x < 256) sb[threadIdx.x] = 0;
    __syncthreads();
    for (int n = blockIdx.x*blockDim.x + threadIdx.x; n < DN; n += gridDim.x*blockDim.x)
        atomicAdd(&sb[(int)(key[n] >> 56)], 1);
    __syncthreads();
    if (threadIdx.x < 256 && sb[threadIdx.x]) atomicAdd(&bins[threadIdx.x], sb[threadIdx.x]);
}

__global__ void select_kernel(int* bins, u64* pfxp, int* remp){
    int rem = *remp;
    u64 pfx = 0ull;
    for (int b = 255; b >= 0; b--){
        int c = bins[b];
        if (rem <= c){ pfx = ((u64)b) << 56; break; }
        rem -= c;
    }
    *remp = rem;
    *pfxp = pfx;
}

__global__ void compact_kernel(const u64* __restrict__ key, const u64* __restrict__ pfxp,
                               u64* __restrict__ cand, int* __restrict__ cnt){
    u64 top = (*pfxp) >> 56;
    int n = blockIdx.x*blockDim.x + threadIdx.x;
    if (n >= DN) return;
    u64 k = key[n];
    if ((k >> 56) == top){
        int p = atomicAdd(cnt, 1);
        cand[p] = k;
    }
}

__global__ void finish_select_kernel(const u64* __restrict__ cand, const int* __restrict__ cntp,
                                     u64* __restrict__ pfxp, int* __restrict__ remp){
    __shared__ int bins[256];
    __shared__ u64 s_pfx;
    __shared__ int s_rem;
    const int tid = threadIdx.x;
    const int C = *cntp;
    if (tid == 0){ s_pfx = *pfxp; s_rem = *remp; }
    __syncthreads();
    for (int shift = 48; shift >= 0; shift -= 8){
        if (tid < 256) bins[tid] = 0;
        __syncthreads();
        u64 pfx = s_pfx;
        for (int i = tid; i < C; i += blockDim.x){
            u64 k = cand[i];
            if ((k >> (shift+8)) == (pfx >> (shift+8)))
                atomicAdd(&bins[(int)((k >> shift) & 0xFF)], 1);
        }
        __syncthreads();
        if (tid == 0){
            int rem = s_rem;
            for (int b = 255; b >= 0; b--){
                int c = bins[b];
                if (rem <= c){ s_pfx = pfx | (((u64)b) << shift); break; }
                rem -= c;
            }
            s_rem = rem;
        }
        __syncthreads();
    }
    if (tid == 0){ *pfxp = s_pfx; *remp = s_rem; }
}

// ---------------- compaction: new_idx for kept nodes ----------------
__global__ void count_kept_kernel(const u64* __restrict__ key, const u64* __restrict__ pfxp,
                                  int* __restrict__ bsum){
    __shared__ int sh[256];
    u64 pfx = *pfxp;
    int tid = threadIdx.x;
    int base = blockIdx.x*1024 + tid*4;
    int c = 0;
    #pragma unroll
    for (int j = 0; j < 4; j++){
        int n = base + j;
        if (n < DN && key[n] >= pfx) c++;
    }
    sh[tid] = c;
    __syncthreads();
    for (int s = 128; s; s >>= 1){
        if (tid < s) sh[tid] += sh[tid + s];
        __syncthreads();
    }
    if (tid == 0) bsum[blockIdx.x] = sh[0];
}

__global__ void scan_kernel(const int* bsum, int* boff){
    int acc = 0;
    for (int i = 0; i < NBLK; i++){ boff[i] = acc; acc += bsum[i]; }
}

__global__ void newidx_kernel(const u64* __restrict__ key, const u64* __restrict__ pfxp,
                              const int* __restrict__ boff, int* __restrict__ newidx){
    __shared__ int sh[256];
    u64 pfx = *pfxp;
    int tid = threadIdx.x;
    int base = blockIdx.x*1024 + tid*4;
    int kept[4]; int cnt = 0;
    #pragma unroll
    for (int j = 0; j < 4; j++){
        int n = base + j;
        kept[j] = (n < DN && key[n] >= pfx) ? 1 : 0;
        cnt += kept[j];
    }
    sh[tid] = cnt;
    __syncthreads();
    for (int s = 1; s < 256; s <<= 1){
        int v = (tid >= s) ? sh[tid - s] : 0;
        __syncthreads();
        sh[tid] += v;
        __syncthreads();
    }
    int off = boff[blockIdx.x] + sh[tid] - cnt;   // exclusive prefix
    #pragma unroll
    for (int j = 0; j < 4; j++){
        int n = base + j;
        if (n < DN) newidx[n] = kept[j] ? off++ : -1;
    }
}

__global__ void build_hp_kernel(const float* __restrict__ H, const int* __restrict__ newidx,
                                const float* __restrict__ score, float* __restrict__ HP){
    int i = blockIdx.x*blockDim.x + threadIdx.x;
    if (i >= DN*32) return;
    int n = i >> 5;
    int ni = newidx[n];
    if (ni < 0) return;
    float s = score[n];
    float4 v = ((const float4*)H)[i];
    v.x *= s; v.y *= s; v.z *= s; v.w *= s;
    ((float4*)HP)[(size_t)ni*32 + (i & 31)] = v;
}

__global__ void remap_kernel(const int* __restrict__ src, const int* __restrict__ dst,
                             const int* __restrict__ newidx,
                             int* __restrict__ ns, int* __restrict__ nd, int* __restrict__ deg){
    int e = blockIdx.x*blockDim.x + threadIdx.x;
    if (e >= DE) return;
    int a = newidx[src[e]];
    int b = newidx[dst[e]];
    if (a >= 0 && b >= 0){
        ns[e] = a; nd[e] = b;
        atomicAdd(&deg[b], 1);
    } else { ns[e] = -1; nd[e] = -1; }
}

// ---------------- launch ----------------
extern "C" void kernel_launch(void* const* d_in, const int* in_sizes, int n_in,
                              void* d_out, int out_size){
    const float* x   = (const float*)d_in[0];
    const int*   ei  = (const int*)  d_in[1];
    const int*   src = ei;
    const int*   dst = ei + DE;
    const float* W1  = (const float*)d_in[3];
    const float* b1  = (const float*)d_in[4];
    const float* pw  = (const float*)d_in[5];
    const float* W2  = (const float*)d_in[6];
    const float* b2  = (const float*)d_in[7];
    const float* W3  = (const float*)d_in[8];
    const float* b3  = (const float*)d_in[9];
    const float* W4  = (const float*)d_in[10];
    const float* b4  = (const float*)d_in[11];
    float* out = (float*)d_out;

    void* basep = nullptr;
    cudaGetSymbolAddress(&basep, g_scratch);
    unsigned char* B = (unsigned char*)basep;
    float* xw    = (float*)(B + OFF_XW);
    float* ha    = (float*)(B + OFF_HA);
    float* hp    = (float*)(B + OFF_HP);
    float* gm    = (float*)(B + OFF_GM);
    float* t2    = (float*)(B + OFF_T2);
    float* dis1  = (float*)(B + OFF_DIS1);
    float* dis2  = (float*)(B + OFF_DIS2);
    int*   deg1  = (int*)  (B + OFF_DEG1);
    int*   deg2  = (int*)  (B + OFF_DEG2);
    int*   rp1   = (int*)  (B + OFF_RP1);
    int*   cur1  = (int*)  (B + OFF_CUR1);
    int*   rp2   = (int*)  (B + OFF_RP2);
    int*   cur2  = (int*)  (B + OFF_CUR2);
    int*   csr1  = (int*)  (B + OFF_CSR1);
    int*   csr2  = (int*)  (B + OFF_CSR2);
    int*   ns    = (int*)  (B + OFF_NS);
    int*   nd    = (int*)  (B + OFF_ND);
    float* score = (float*)(B + OFF_SCORE);
    u64*   key   = (u64*)  (B + OFF_KEY);
    u64*   cand  = (u64*)  (B + OFF_CAND);
    int*   nidx  = (int*)  (B + OFF_NEW);
    int*   bins  = (int*)  (B + OFF_BINS);
    int*   bsum  = (int*)  (B + OFF_BSUM);
    int*   boff  = (int*)  (B + OFF_BOFF);
    u64*   pfx   = (u64*)  (B + OFF_PFX);
    int*   rem   = (int*)  (B + OFF_REM);
    float* wn    = (float*)(B + OFF_WN);
    int*   ccnt  = (int*)  (B + OFF_CCNT);
    int*   syn   = (int*)  (B + OFF_SYNC);
    float* acc   = (float*)(B + OFF_ACC);

    const int T = 256;
    const int NB1 = (DN + 1023)/1024;   // 49
    const int NB2 = (DK + 1023)/1024;   // 40
    const int SMEM_G1 = (64*128 + 64*64)*4;     // 48 KB  (KIN=64, KOUT=128, ROWS=64)
    const int SMEM_G2 = (128*64 + 128*128)*4;   // 96 KB  (KIN=128, KOUT=64, ROWS=128)
    cudaFuncSetAttribute(gemm8t<128,64,128>, cudaFuncAttributeMaxDynamicSharedMemorySize, SMEM_G2);
    cudaFuncSetAttribute(gemm8t<64,128,64>,  cudaFuncAttributeMaxDynamicSharedMemorySize, SMEM_G1);

    // reset all per-replay state
    init_kernel<<<(DN+T-1)/T, T>>>(deg1, deg2, bins, acc, rem, pfx, ccnt, syn);

    // ---- graph structure for conv1 ----
    deg_kernel<<<(DE+T-1)/T, T>>>(dst, deg1);
    fused_scan_kernel<<<NB1, 1024>>>(deg1, bsum, boff, syn+0, syn+1, rp1, cur1, dis1, DN, NB1);
    scatter1_kernel<<<(DE+T-1)/T, T>>>(src, dst, cur1, csr1);

    // ---- conv1: gemm (dis-scaled) + gather + relu ----
    gemm8t<64,128,64><<<(DN+63)/64, 128, SMEM_G1>>>(x, W1, dis1, xw, DN);
    gather128_kernel<true><<<(DN*32+T-1)/T, T>>>(rp1, csr1, dis1, xw, b1, ha, DN);

    // ---- TopK pooling (exact radix select) ----
    wnorm_kernel<<<1,128>>>(pw, wn);
    score_kernel<<<(DN*32+T-1)/T, T>>>(ha, pw, wn, score, key);
    hist_kernel<<<128, T>>>(key, bins);
    select_kernel<<<1,1>>>(bins, pfx, rem);
    compact_kernel<<<(DN+T-1)/T, T>>>(key, pfx, cand, ccnt);
    finish_select_kernel<<<1, 1024>>>(cand, ccnt, pfx, rem);
    count_kept_kernel<<<NBLK, T>>>(key, pfx, bsum);
    scan_kernel<<<1,1>>>(bsum, boff);
    newidx_kernel<<<NBLK, T>>>(key, pfx, boff, nidx);
    build_hp_kernel<<<(DN*32+T-1)/T, T>>>(ha, nidx, score, hp);
    remap_kernel<<<(DE+T-1)/T, T>>>(src, dst, nidx, ns, nd, deg2);
    fused_scan_kernel<<<NB2, 1024>>>(deg2, bsum, boff, syn+2, syn+3, rp2, cur2, dis2, DK, NB2);
    scatter2_kernel<<<(DE+T-1)/T, T>>>(ns, nd, cur2, csr2);

    // ---- conv2 (128 -> 64) + relu ----
    gemm8t<128,64,128><<<(DK+127)/128, 128, SMEM_G2>>>(hp, W2, dis2, gm, DK);
    gather64_kernel<true><<<(DK*16+T-1)/T, T>>>(rp2, csr2, dis2, gm, b2, t2, DK);

    // ---- conv3 (64 -> 128) + relu ----
    gemm8t<64,128,64><<<(DK+63)/64, 128, SMEM_G1>>>(t2, W3, dis2, xw, DK);
    gather128_kernel<true><<<(DK*32+T-1)/T, T>>>(rp2, csr2, dis2, xw, b3, ha, DK);

    // ---- conv4 (128 -> 64), fused with global mean ----
    gemm8t<128,64,128><<<(DK+127)/128, 128, SMEM_G2>>>(ha, W4, dis2, gm, DK);
    gather64_reduce_kernel<<<296, T>>>(rp2, csr2, dis2, gm, acc);
    write_out_kernel<<<1,64>>>(acc, b4, out);
}

// round 8
// speedup vs baseline: 1.2973x; 1.2973x over previous
#include <cuda_runtime.h>

typedef unsigned long long u64;

#define DN 50000
#define DE 800000
#define DK 40000
#define NBLK 49   // ceil(DN/1024) for the kept-node compaction

// ---------------- scratch layout (single __device__ blob) ----------------
static constexpr size_t OFF_XW   = 0;                               // DN*128 gemm out
static constexpr size_t OFF_HA   = OFF_XW  + (size_t)DN*128*4;      // DN*128 gather out
static constexpr size_t OFF_HP   = OFF_HA  + (size_t)DN*128*4;      // DK*128 pooled feats
static constexpr size_t OFF_GM   = OFF_HP  + (size_t)DK*128*4;      // DK*64 gemm out
static constexpr size_t OFF_T2   = OFF_GM  + (size_t)DK*64*4;       // DK*64 gather out
static constexpr size_t OFF_DIS1 = OFF_T2  + (size_t)DK*64*4;       // DN
static constexpr size_t OFF_DIS2 = OFF_DIS1 + (size_t)DN*4;         // DK
static constexpr size_t OFF_DEG1 = OFF_DIS2 + (size_t)DK*4;         // DN
static constexpr size_t OFF_DEG2 = OFF_DEG1 + (size_t)DN*4;         // DK
static constexpr size_t OFF_RP1  = OFF_DEG2 + (size_t)DK*4;         // DN+1
static constexpr size_t OFF_CUR1 = OFF_RP1  + (size_t)(DN+1)*4;     // DN
static constexpr size_t OFF_RP2  = OFF_CUR1 + (size_t)DN*4;         // DK+1
static constexpr size_t OFF_CUR2 = OFF_RP2  + (size_t)(DK+1)*4;     // DK
static constexpr size_t OFF_CSR1 = OFF_CUR2 + (size_t)DK*4;         // DE
static constexpr size_t OFF_CSR2 = OFF_CSR1 + (size_t)DE*4;         // DE
static constexpr size_t OFF_NS   = OFF_CSR2 + (size_t)DE*4;         // DE
static constexpr size_t OFF_ND   = OFF_NS   + (size_t)DE*4;         // DE
static constexpr size_t OFF_SCORE= OFF_ND   + (size_t)DE*4;         // DN
static constexpr size_t OFF_KEY  = OFF_SCORE+ (size_t)DN*4;         // DN u64
static constexpr size_t OFF_CAND = OFF_KEY  + (size_t)DN*8;         // DN u64 (boundary-bin candidates)
static constexpr size_t OFF_NEW  = OFF_CAND + (size_t)DN*8;         // DN
static constexpr size_t OFF_BINS = OFF_NEW  + (size_t)DN*4;
static constexpr size_t OFF_BSUM = OFF_BINS + 256*4;                // 64 (scan partials & compaction)
static constexpr size_t OFF_BOFF = OFF_BSUM + 64*4;
static constexpr size_t OFF_PFX  = OFF_BOFF + 64*4;
static constexpr size_t OFF_REM  = OFF_PFX  + 8;
static constexpr size_t OFF_WN   = OFF_REM  + 4;
static constexpr size_t OFF_CCNT = OFF_WN   + 4;
static constexpr size_t OFF_ACC  = OFF_CCNT + 4;
static constexpr size_t TOTAL_BYTES = OFF_ACC + 64*4;

__device__ __align__(256) unsigned char g_scratch[TOTAL_BYTES];

// ---------------- init: reset all per-replay state in one launch ------------
__global__ void init_kernel(int* deg1, int* deg2, int* bins, float* acc,
                            int* rem, u64* pfx, int* ccnt){
    int i = blockIdx.x*blockDim.x + threadIdx.x;
    if (i < DN)  deg1[i] = 0;
    if (i < DK)  deg2[i] = 0;
    if (i < 256) bins[i] = 0;
    if (i < 64)  acc[i]  = 0.f;
    if (i == 0){ *rem = DK; *pfx = 0ull; *ccnt = 0; }
}

// ---------------- register-tiled GEMM (R5-proven): Y = X @ W ----------------
template<int KIN, int KOUT, int ROWS>
__global__ void gemm_rt(const float* __restrict__ X, const float* __restrict__ W,
                        float* __restrict__ Y, int M){
    extern __shared__ float sm[];
    float* sW = sm;                 // KIN*KOUT
    float* sX = sm + KIN*KOUT;      // ROWS*KIN
    const int tid = threadIdx.x;
    constexpr int CG = KOUT/4;
    constexpr int RG = ROWS/4;
    for (int i = tid; i < KIN*KOUT/4; i += blockDim.x)
        ((float4*)sW)[i] = ((const float4*)W)[i];
    const int row0 = blockIdx.x * ROWS;
    for (int i = tid; i < ROWS*KIN/4; i += blockDim.x){
        int r  = i / (KIN/4);
        int gr = row0 + r;
        ((float4*)sX)[i] = (gr < M) ? ((const float4*)X)[(size_t)gr*(KIN/4) + (i % (KIN/4))]
                                    : make_float4(0.f,0.f,0.f,0.f);
    }
    __syncthreads();
    const float4* w4 = (const float4*)sW;
    for (int it = tid; it < RG*CG; it += blockDim.x){
        int rg = it / CG, cg = it % CG;
        int r0 = rg*4;
        float4 a0 = make_float4(0,0,0,0), a1 = a0, a2 = a0, a3 = a0;
        #pragma unroll 8
        for (int k = 0; k < KIN; k++){
            float4 w = w4[k*CG + cg];
            float x0 = sX[(r0+0)*KIN + k];
            float x1 = sX[(r0+1)*KIN + k];
            float x2 = sX[(r0+2)*KIN + k];
            float x3 = sX[(r0+3)*KIN + k];
            a0.x += x0*w.x; a0.y += x0*w.y; a0.z += x0*w.z; a0.w += x0*w.w;
            a1.x += x1*w.x; a1.y += x1*w.y; a1.z += x1*w.z; a1.w += x1*w.w;
            a2.x += x2*w.x; a2.y += x2*w.y; a2.z += x2*w.z; a2.w += x2*w.w;
            a3.x += x3*w.x; a3.y += x3*w.y; a3.z += x3*w.z; a3.w += x3*w.w;
        }
        float4* yp = (float4*)Y;
        int gr = row0 + r0;
        if (gr+0 < M) yp[(size_t)(gr+0)*CG + cg] = a0;
        if (gr+1 < M) yp[(size_t)(gr+1)*CG + cg] = a1;
        if (gr+2 < M) yp[(size_t)(gr+2)*CG + cg] = a2;
        if (gr+3 < M) yp[(size_t)(gr+3)*CG + cg] = a3;
    }
}

// ---------------- degree histogram ----------------
__global__ void deg_kernel(const int* __restrict__ dst, int* __restrict__ deg){
    int e = blockIdx.x*blockDim.x + threadIdx.x;
    if (e < DE) atomicAdd(&deg[dst[e]], 1);
}

// ---------------- 3-phase device-wide scan (R5-proven) ----------------
__global__ void blocksum_kernel(const int* __restrict__ deg, int* __restrict__ bsums, int M){
    __shared__ int sh[256];
    int tid = threadIdx.x;
    int base = blockIdx.x * 1024;
    int s = 0;
    #pragma unroll
    for (int j = 0; j < 4; j++){
        int i = base + tid + j*256;
        if (i < M) s += deg[i];
    }
    sh[tid] = s;
    __syncthreads();
    for (int o = 128; o; o >>= 1){
        if (tid < o) sh[tid] += sh[tid + o];
        __syncthreads();
    }
    if (tid == 0) bsums[blockIdx.x] = sh[0];
}

__global__ void bscan_kernel(int* __restrict__ bsums, int nb){
    if (threadIdx.x == 0){
        int acc = 0;
        for (int i = 0; i < nb; i++){ int v = bsums[i]; bsums[i] = acc; acc += v; }
    }
}

__global__ void scanwrite_kernel(const int* __restrict__ deg, const int* __restrict__ bsums,
                                 int* __restrict__ rowptr, int* __restrict__ cur,
                                 float* __restrict__ dis, int M){
    __shared__ int sh[1024];
    int tid = threadIdx.x;
    int i = blockIdx.x*1024 + tid;
    int v = (i < M) ? deg[i] : 0;
    sh[tid] = v;
    __syncthreads();
    #pragma unroll
    for (int o = 1; o < 1024; o <<= 1){
        int t = (tid >= o) ? sh[tid - o] : 0;
        __syncthreads();
        sh[tid] += t;
        __syncthreads();
    }
    if (i < M){
        int excl = bsums[blockIdx.x] + sh[tid] - v;
        rowptr[i] = excl;
        cur[i]    = excl;
        dis[i]    = rsqrtf(1.0f + (float)v);
        if (i == M-1) rowptr[M] = excl + v;
    }
}

// ---------------- CSR scatter ----------------
__global__ void scatter1_kernel(const int* __restrict__ src, const int* __restrict__ dst,
                                int* __restrict__ cur, int* __restrict__ csr){
    int e = blockIdx.x*blockDim.x + threadIdx.x;
    if (e >= DE) return;
    int pos = atomicAdd(&cur[dst[e]], 1);
    csr[pos] = src[e];
}

__global__ void scatter2_kernel(const int* __restrict__ ns, const int* __restrict__ nd,
                                int* __restrict__ cur, int* __restrict__ csr){
    int e = blockIdx.x*blockDim.x + threadIdx.x;
    if (e >= DE) return;
    int a = ns[e];
    if (a < 0) return;
    int pos = atomicAdd(&cur[nd[e]], 1);
    csr[pos] = a;
}

// ---------------- CSR gather + fused GCN epilogue (R5-proven) ----------------
template<bool RELU>
__global__ void gather128_kernel(const int* __restrict__ rowptr, const int* __restrict__ csr,
                                 const float* __restrict__ dis, const float* __restrict__ Hin,
                                 const float* __restrict__ bias, float* __restrict__ Hout, int M){
    int w = (blockIdx.x*blockDim.x + threadIdx.x) >> 5;
    int lane = threadIdx.x & 31;
    if (w >= M) return;
    int beg = rowptr[w], end = rowptr[w+1];
    float dn = dis[w];
    float4 h = ((const float4*)Hin)[(size_t)w*32 + lane];
    float s2 = dn*dn;
    float4 acc = make_float4(h.x*s2, h.y*s2, h.z*s2, h.w*s2);
    for (int j = beg; j < end; j++){
        int s = csr[j];
        float c = dis[s] * dn;
        float4 v = ((const float4*)Hin)[(size_t)s*32 + lane];
        acc.x += c*v.x; acc.y += c*v.y; acc.z += c*v.z; acc.w += c*v.w;
    }
    float4 b = ((const float4*)bias)[lane];
    acc.x += b.x; acc.y += b.y; acc.z += b.z; acc.w += b.w;
    if (RELU){
        acc.x = fmaxf(acc.x, 0.f); acc.y = fmaxf(acc.y, 0.f);
        acc.z = fmaxf(acc.z, 0.f); acc.w = fmaxf(acc.w, 0.f);
    }
    ((float4*)Hout)[(size_t)w*32 + lane] = acc;
}

template<bool RELU>
__global__ void gather64_kernel(const int* __restrict__ rowptr, const int* __restrict__ csr,
                                const float* __restrict__ dis, const float* __restrict__ Hin,
                                const float* __restrict__ bias, float* __restrict__ Hout, int M){
    int w = (blockIdx.x*blockDim.x + threadIdx.x) >> 5;
    int lane = threadIdx.x & 31;
    if (w >= M) return;
    int beg = rowptr[w], end = rowptr[w+1];
    float dn = dis[w];
    float2 h = ((const float2*)Hin)[(size_t)w*32 + lane];
    float s2 = dn*dn;
    float2 acc = make_float2(h.x*s2, h.y*s2);
    for (int j = beg; j < end; j++){
        int s = csr[j];
        float c = dis[s] * dn;
        float2 v = ((const float2*)Hin)[(size_t)s*32 + lane];
        acc.x += c*v.x; acc.y += c*v.y;
    }
    float2 b = ((const float2*)bias)[lane];
    acc.x += b.x; acc.y += b.y;
    if (RELU){ acc.x = fmaxf(acc.x, 0.f); acc.y = fmaxf(acc.y, 0.f); }
    ((float2*)Hout)[(size_t)w*32 + lane] = acc;
}

// conv4 gather fused with the global mean accumulation (bias added at writeout)
__global__ void gather64_reduce_kernel(const int* __restrict__ rowptr, const int* __restrict__ csr,
                                       const float* __restrict__ dis, const float* __restrict__ Hin,
                                       float* __restrict__ accOut){
    __shared__ float sh[64];
    const int lane = threadIdx.x & 31;
    const int wloc = threadIdx.x >> 5;
    const int wpb  = blockDim.x >> 5;
    if (threadIdx.x < 64) sh[threadIdx.x] = 0.f;
    __syncthreads();
    int w = blockIdx.x*wpb + wloc;
    int tw = gridDim.x*wpb;
    float2 sum = make_float2(0.f, 0.f);
    for (int n = w; n < DK; n += tw){
        int beg = rowptr[n], end = rowptr[n+1];
        float dn = dis[n];
        float2 h = ((const float2*)Hin)[(size_t)n*32 + lane];
        float s2 = dn*dn;
        float2 a = make_float2(h.x*s2, h.y*s2);
        for (int j = beg; j < end; j++){
            int s = csr[j];
            float c = dis[s] * dn;
            float2 v = ((const float2*)Hin)[(size_t)s*32 + lane];
            a.x += c*v.x; a.y += c*v.y;
        }
        sum.x += a.x; sum.y += a.y;
    }
    atomicAdd(&sh[2*lane],   sum.x);
    atomicAdd(&sh[2*lane+1], sum.y);
    __syncthreads();
    if (threadIdx.x < 64) atomicAdd(&accOut[threadIdx.x], sh[threadIdx.x]);
}

__global__ void write_out_kernel(const float* __restrict__ acc, const float* __restrict__ b4,
                                 float* __restrict__ out){
    if (threadIdx.x < 64)
        out[threadIdx.x] = acc[threadIdx.x] * (1.0f/(float)DK) + b4[threadIdx.x];
}

// ---------------- pooling: score + collapsed exact top-K radix select -------
__global__ void wnorm_kernel(const float* __restrict__ w, float* wn){
    float v = w[threadIdx.x]; v *= v;
    #pragma unroll
    for (int o = 16; o; o >>= 1) v += __shfl_xor_sync(0xffffffffu, v, o);
    __shared__ float sh[4];
    if ((threadIdx.x & 31) == 0) sh[threadIdx.x >> 5] = v;
    __syncthreads();
    if (threadIdx.x == 0) *wn = sqrtf(sh[0]+sh[1]+sh[2]+sh[3]);
}

__global__ void score_kernel(const float* __restrict__ H, const float* __restrict__ w,
                             const float* __restrict__ wn,
                             float* __restrict__ score, u64* __restrict__ key){
    int t = blockIdx.x*blockDim.x + threadIdx.x;
    int n = t >> 5, lane = t & 31;
    if (n >= DN) return;
    float4 a = ((const float4*)H)[(size_t)n*32 + lane];
    float4 b = ((const float4*)w)[lane];
    float s = a.x*b.x + a.y*b.y + a.z*b.z + a.w*b.w;
    #pragma unroll
    for (int o = 16; o; o >>= 1) s += __shfl_xor_sync(0xffffffffu, s, o);
    if (lane == 0){
        s = tanhf(s / *wn);
        score[n] = s;
        unsigned ub = __float_as_uint(s);
        ub = (ub & 0x80000000u) ? ~ub : (ub | 0x80000000u);   // order-preserving map
        key[n] = ((u64)ub << 32) | (u64)(0xffffffffu - (unsigned)n);  // distinct keys
    }
}

// single full-histogram pass over the top byte
__global__ void hist_kernel(const u64* __restrict__ key, int* __restrict__ bins){
    __shared__ int sb[256];
    if (threadIdx.x < 256) sb[threadIdx.x] = 0;
    __syncthreads();
    for (int n = blockIdx.x*blockDim.x + threadIdx.x; n < DN; n += gridDim.x*blockDim.x)
        atomicAdd(&sb[(int)(key[n] >> 56)], 1);
    __syncthreads();
    if (threadIdx.x < 256 && sb[threadIdx.x]) atomicAdd(&bins[threadIdx.x], sb[threadIdx.x]);
}

__global__ void select_kernel(int* bins, u64* pfxp, int* remp){
    int rem = *remp;
    u64 pfx = 0ull;
    for (int b = 255; b >= 0; b--){
        int c = bins[b];
        if (rem <= c){ pfx = ((u64)b) << 56; break; }
        rem -= c;
    }
    *remp = rem;
    *pfxp = pfx;
}

// collect keys whose top byte equals the boundary byte
__global__ void compact_kernel(const u64* __restrict__ key, const u64* __restrict__ pfxp,
                               u64* __restrict__ cand, int* __restrict__ cnt){
    u64 top = (*pfxp) >> 56;
    int n = blockIdx.x*blockDim.x + threadIdx.x;
    if (n >= DN) return;
    u64 k = key[n];
    if ((k >> 56) == top){
        int p = atomicAdd(cnt, 1);
        cand[p] = k;
    }
}

// remaining 7 radix passes in one block over the few candidates
__global__ void finish_select_kernel(const u64* __restrict__ cand, const int* __restrict__ cntp,
                                     u64* __restrict__ pfxp, int* __restrict__ remp){
    __shared__ int bins[256];
    __shared__ u64 s_pfx;
    __shared__ int s_rem;
    const int tid = threadIdx.x;
    const int C = *cntp;
    if (tid == 0){ s_pfx = *pfxp; s_rem = *remp; }
    __syncthreads();
    for (int shift = 48; shift >= 0; shift -= 8){
        if (tid < 256) bins[tid] = 0;
        __syncthreads();
        u64 pfx = s_pfx;
        for (int i = tid; i < C; i += blockDim.x){
            u64 k = cand[i];
            if ((k >> (shift+8)) == (pfx >> (shift+8)))
                atomicAdd(&bins[(int)((k >> shift) & 0xFF)], 1);
        }
        __syncthreads();
        if (tid == 0){
            int rem = s_rem;
            for (int b = 255; b >= 0; b--){
                int c = bins[b];
                if (rem <= c){ s_pfx = pfx | (((u64)b) << shift); break; }
                rem -= c;
            }
            s_rem = rem;
        }
        __syncthreads();
    }
    if (tid == 0){ *pfxp = s_pfx; *remp = s_rem; }
}

// ---------------- compaction: new_idx for kept nodes ----------------
__global__ void count_kept_kernel(const u64* __restrict__ key, const u64* __restrict__ pfxp,
                                  int* __restrict__ bsum){
    __shared__ int sh[256];
    u64 pfx = *pfxp;
    int tid = threadIdx.x;
    int base = blockIdx.x*1024 + tid*4;
    int c = 0;
    #pragma unroll
    for (int j = 0; j < 4; j++){
        int n = base + j;
        if (n < DN && key[n] >= pfx) c++;
    }
    sh[tid] = c;
    __syncthreads();
    for (int s = 128; s; s >>= 1){
        if (tid < s) sh[tid] += sh[tid + s];
        __syncthreads();
    }
    if (tid == 0) bsum[blockIdx.x] = sh[0];
}

__global__ void scan_kernel(const int* bsum, int* boff){
    int acc = 0;
    for (int i = 0; i < NBLK; i++){ boff[i] = acc; acc += bsum[i]; }
}

__global__ void newidx_kernel(const u64* __restrict__ key, const u64* __restrict__ pfxp,
                              const int* __restrict__ boff, int* __restrict__ newidx){
    __shared__ int sh[256];
    u64 pfx = *pfxp;
    int tid = threadIdx.x;
    int base = blockIdx.x*1024 + tid*4;
    int kept[4]; int cnt = 0;
    #pragma unroll
    for (int j = 0; j < 4; j++){
        int n = base + j;
        kept[j] = (n < DN && key[n] >= pfx) ? 1 : 0;
        cnt += kept[j];
    }
    sh[tid] = cnt;
    __syncthreads();
    for (int s = 1; s < 256; s <<= 1){
        int v = (tid >= s) ? sh[tid - s] : 0;
        __syncthreads();
        sh[tid] += v;
        __syncthreads();
    }
    int off = boff[blockIdx.x] + sh[tid] - cnt;   // exclusive prefix
    #pragma unroll
    for (int j = 0; j < 4; j++){
        int n = base + j;
        if (n < DN) newidx[n] = kept[j] ? off++ : -1;
    }
}

__global__ void build_hp_kernel(const float* __restrict__ H, const int* __restrict__ newidx,
                                const float* __restrict__ score, float* __restrict__ HP){
    int i = blockIdx.x*blockDim.x + threadIdx.x;
    if (i >= DN*32) return;
    int n = i >> 5;
    int ni = newidx[n];
    if (ni < 0) return;
    float s = score[n];
    float4 v = ((const float4*)H)[i];
    v.x *= s; v.y *= s; v.z *= s; v.w *= s;
    ((float4*)HP)[(size_t)ni*32 + (i & 31)] = v;
}

__global__ void remap_kernel(const int* __restrict__ src, const int* __restrict__ dst,
                             const int* __restrict__ newidx,
                             int* __restrict__ ns, int* __restrict__ nd, int* __restrict__ deg){
    int e = blockIdx.x*blockDim.x + threadIdx.x;
    if (e >= DE) return;
    int a = newidx[src[e]];
    int b = newidx[dst[e]];
    if (a >= 0 && b >= 0){
        ns[e] = a; nd[e] = b;
        atomicAdd(&deg[b], 1);
    } else { ns[e] = -1; nd[e] = -1; }
}

// ---------------- launch ----------------
extern "C" void kernel_launch(void* const* d_in, const int* in_sizes, int n_in,
                              void* d_out, int out_size){
    const float* x   = (const float*)d_in[0];
    const int*   ei  = (const int*)  d_in[1];
    const int*   src = ei;
    const int*   dst = ei + DE;
    const float* W1  = (const float*)d_in[3];
    const float* b1  = (const float*)d_in[4];
    const float* pw  = (const float*)d_in[5];
    const float* W2  = (const float*)d_in[6];
    const float* b2  = (const float*)d_in[7];
    const float* W3  = (const float*)d_in[8];
    const float* b3  = (const float*)d_in[9];
    const float* W4  = (const float*)d_in[10];
    const float* b4  = (const float*)d_in[11];
    float* out = (float*)d_out;

    void* basep = nullptr;
    cudaGetSymbolAddress(&basep, g_scratch);
    unsigned char* B = (unsigned char*)basep;
    float* xw    = (float*)(B + OFF_XW);
    float* ha    = (float*)(B + OFF_HA);
    float* hp    = (float*)(B + OFF_HP);
    float* gm    = (float*)(B + OFF_GM);
    float* t2    = (float*)(B + OFF_T2);
    float* dis1  = (float*)(B + OFF_DIS1);
    float* dis2  = (float*)(B + OFF_DIS2);
    int*   deg1  = (int*)  (B + OFF_DEG1);
    int*   deg2  = (int*)  (B + OFF_DEG2);
    int*   rp1   = (int*)  (B + OFF_RP1);
    int*   cur1  = (int*)  (B + OFF_CUR1);
    int*   rp2   = (int*)  (B + OFF_RP2);
    int*   cur2  = (int*)  (B + OFF_CUR2);
    int*   csr1  = (int*)  (B + OFF_CSR1);
    int*   csr2  = (int*)  (B + OFF_CSR2);
    int*   ns    = (int*)  (B + OFF_NS);
    int*   nd    = (int*)  (B + OFF_ND);
    float* score = (float*)(B + OFF_SCORE);
    u64*   key   = (u64*)  (B + OFF_KEY);
    u64*   cand  = (u64*)  (B + OFF_CAND);
    int*   nidx  = (int*)  (B + OFF_NEW);
    int*   bins  = (int*)  (B + OFF_BINS);
    int*   bsum  = (int*)  (B + OFF_BSUM);
    int*   boff  = (int*)  (B + OFF_BOFF);
    u64*   pfx   = (u64*)  (B + OFF_PFX);
    int*   rem   = (int*)  (B + OFF_REM);
    float* wn    = (float*)(B + OFF_WN);
    int*   ccnt  = (int*)  (B + OFF_CCNT);
    float* acc   = (float*)(B + OFF_ACC);

    const int T = 256;
    const int NB1 = (DN + 1023)/1024;   // 49
    const int NB2 = (DK + 1023)/1024;   // 40
    const int SMEM_G1 = (64*128 + 64*64)*4;    // 48 KB
    const int SMEM_G2 = (128*64 + 64*128)*4;   // 64 KB (needs opt-in)
    cudaFuncSetAttribute(gemm_rt<128,64,64>, cudaFuncAttributeMaxDynamicSharedMemorySize, SMEM_G2);

    // reset all per-replay state
    init_kernel<<<(DN+T-1)/T, T>>>(deg1, deg2, bins, acc, rem, pfx, ccnt);

    // ---- conv1 on full graph (CSR gather) ----
    gemm_rt<64,128,64><<<(DN+63)/64, T, SMEM_G1>>>(x, W1, xw, DN);
    deg_kernel<<<(DE+T-1)/T, T>>>(dst, deg1);
    blocksum_kernel<<<NB1, 256>>>(deg1, bsum, DN);
    bscan_kernel<<<1, 32>>>(bsum, NB1);
    scanwrite_kernel<<<NB1, 1024>>>(deg1, bsum, rp1, cur1, dis1, DN);
    scatter1_kernel<<<(DE+T-1)/T, T>>>(src, dst, cur1, csr1);
    gather128_kernel<true><<<(DN*32+T-1)/T, T>>>(rp1, csr1, dis1, xw, b1, ha, DN);

    // ---- TopK pooling (exact radix select, collapsed to 4 launches) ----
    wnorm_kernel<<<1,128>>>(pw, wn);
    score_kernel<<<(DN*32+T-1)/T, T>>>(ha, pw, wn, score, key);
    hist_kernel<<<128, T>>>(key, bins);
    select_kernel<<<1,1>>>(bins, pfx, rem);
    compact_kernel<<<(DN+T-1)/T, T>>>(key, pfx, cand, ccnt);
    finish_select_kernel<<<1, 1024>>>(cand, ccnt, pfx, rem);
    count_kept_kernel<<<NBLK, T>>>(key, pfx, bsum);
    scan_kernel<<<1,1>>>(bsum, boff);
    newidx_kernel<<<NBLK, T>>>(key, pfx, boff, nidx);
    build_hp_kernel<<<(DN*32+T-1)/T, T>>>(ha, nidx, score, hp);
    remap_kernel<<<(DE+T-1)/T, T>>>(src, dst, nidx, ns, nd, deg2);
    blocksum_kernel<<<NB2, 256>>>(deg2, bsum, DK);
    bscan_kernel<<<1, 32>>>(bsum, NB2);
    scanwrite_kernel<<<NB2, 1024>>>(deg2, bsum, rp2, cur2, dis2, DK);
    scatter2_kernel<<<(DE+T-1)/T, T>>>(ns, nd, cur2, csr2);

    // ---- conv2 (128 -> 64) + relu ----
    gemm_rt<128,64,64><<<(DK+63)/64, T, SMEM_G2>>>(hp, W2, gm, DK);
    gather64_kernel<true><<<(DK*32+T-1)/T, T>>>(rp2, csr2, dis2, gm, b2, t2, DK);

    // ---- conv3 (64 -> 128) + relu ----
    gemm_rt<64,128,64><<<(DK+63)/64, T, SMEM_G1>>>(t2, W3, xw, DK);
    gather128_kernel<true><<<(DK*32+T-1)/T, T>>>(rp2, csr2, dis2, xw, b3, ha, DK);

    // ---- conv4 (128 -> 64), fused with global mean ----
    gemm_rt<128,64,64><<<(DK+63)/64, T, SMEM_G2>>>(ha, W4, gm, DK);
    gather64_reduce_kernel<<<296, T>>>(rp2, csr2, dis2, gm, acc);
    write_out_kernel<<<1,64>>>(acc, b4, out);
}

// round 9
// speedup vs baseline: 1.3530x; 1.0430x over previous
#include <cuda_runtime.h>

typedef unsigned long long u64;

#define DN 50000
#define DE 800000
#define DK 40000
#define NBLK 49   // ceil(DN/1024) for the kept-node compaction

// ---------------- scratch layout (single __device__ blob) ----------------
static constexpr size_t OFF_XA   = 0;                               // DN*128 (gather-raw out, reused)
static constexpr size_t OFF_HA   = OFF_XA  + (size_t)DN*128*4;      // DN*128 conv out
static constexpr size_t OFF_HP   = OFF_HA  + (size_t)DN*128*4;      // DK*128 pooled feats
static constexpr size_t OFF_GM   = OFF_HP  + (size_t)DK*128*4;      // DK*64 gemm out
static constexpr size_t OFF_T2   = OFF_GM  + (size_t)DK*64*4;       // DK*64 conv2 out
static constexpr size_t OFF_DIS1 = OFF_T2  + (size_t)DK*64*4;       // DN
static constexpr size_t OFF_DIS2 = OFF_DIS1 + (size_t)DN*4;         // DK
static constexpr size_t OFF_DEG1 = OFF_DIS2 + (size_t)DK*4;         // DN
static constexpr size_t OFF_DEG2 = OFF_DEG1 + (size_t)DN*4;         // DK
static constexpr size_t OFF_RP1  = OFF_DEG2 + (size_t)DK*4;         // DN+1
static constexpr size_t OFF_CUR1 = OFF_RP1  + (size_t)(DN+1)*4;     // DN
static constexpr size_t OFF_RP2  = OFF_CUR1 + (size_t)DN*4;         // DK+1
static constexpr size_t OFF_CUR2 = OFF_RP2  + (size_t)(DK+1)*4;     // DK
static constexpr size_t OFF_CSR1 = OFF_CUR2 + (size_t)DK*4;         // DE
static constexpr size_t OFF_CSR2 = OFF_CSR1 + (size_t)DE*4;         // DE
static constexpr size_t OFF_NS   = OFF_CSR2 + (size_t)DE*4;         // DE
static constexpr size_t OFF_ND   = OFF_NS   + (size_t)DE*4;         // DE
static constexpr size_t OFF_SCORE= OFF_ND   + (size_t)DE*4;         // DN
static constexpr size_t OFF_KEY  = OFF_SCORE+ (size_t)DN*4;         // DN u64
static constexpr size_t OFF_CAND = OFF_KEY  + (size_t)DN*8;         // DN u64
static constexpr size_t OFF_NEW  = OFF_CAND + (size_t)DN*8;         // DN
static constexpr size_t OFF_BINS = OFF_NEW  + (size_t)DN*4;
static constexpr size_t OFF_BSUM = OFF_BINS + 256*4;                // 64
static constexpr size_t OFF_PFX  = OFF_BSUM + 64*4;
static constexpr size_t OFF_REM  = OFF_PFX  + 8;
static constexpr size_t OFF_CCNT = OFF_REM  + 4;
static constexpr size_t OFF_ACC  = OFF_CCNT + 4;
static constexpr size_t TOTAL_BYTES = OFF_ACC + 64*4;

__device__ __align__(256) unsigned char g_scratch[TOTAL_BYTES];

// ---------------- init: reset all per-replay state in one launch ------------
__global__ void init_kernel(int* deg1, int* deg2, int* bins, float* acc, int* ccnt){
    int i = blockIdx.x*blockDim.x + threadIdx.x;
    if (i < DN)  deg1[i] = 0;
    if (i < DK)  deg2[i] = 0;
    if (i < 256) bins[i] = 0;
    if (i < 64)  acc[i]  = 0.f;
    if (i == 0)  *ccnt = 0;
}

// ---------------- register-tiled GEMM (R5-proven) + optional bias/relu epi --
// EPI: Y = relu(X@W + b)   else Y = X@W
template<int KIN, int KOUT, int ROWS, bool EPI>
__global__ void gemm_rt(const float* __restrict__ X, const float* __restrict__ W,
                        const float* __restrict__ bias, float* __restrict__ Y, int M){
    extern __shared__ float sm[];
    float* sW = sm;                 // KIN*KOUT
    float* sX = sm + KIN*KOUT;      // ROWS*KIN
    const int tid = threadIdx.x;
    constexpr int CG = KOUT/4;
    constexpr int RG = ROWS/4;
    for (int i = tid; i < KIN*KOUT/4; i += blockDim.x)
        ((float4*)sW)[i] = ((const float4*)W)[i];
    const int row0 = blockIdx.x * ROWS;
    for (int i = tid; i < ROWS*KIN/4; i += blockDim.x){
        int r  = i / (KIN/4);
        int gr = row0 + r;
        ((float4*)sX)[i] = (gr < M) ? ((const float4*)X)[(size_t)gr*(KIN/4) + (i % (KIN/4))]
                                    : make_float4(0.f,0.f,0.f,0.f);
    }
    __syncthreads();
    const float4* w4 = (const float4*)sW;
    for (int it = tid; it < RG*CG; it += blockDim.x){
        int rg = it / CG, cg = it % CG;
        int r0 = rg*4;
        float4 a0 = make_float4(0,0,0,0), a1 = a0, a2 = a0, a3 = a0;
        #pragma unroll 8
        for (int k = 0; k < KIN; k++){
            float4 w = w4[k*CG + cg];
            float x0 = sX[(r0+0)*KIN + k];
            float x1 = sX[(r0+1)*KIN + k];
            float x2 = sX[(r0+2)*KIN + k];
            float x3 = sX[(r0+3)*KIN + k];
            a0.x += x0*w.x; a0.y += x0*w.y; a0.z += x0*w.z; a0.w += x0*w.w;
            a1.x += x1*w.x; a1.y += x1*w.y; a1.z += x1*w.z; a1.w += x1*w.w;
            a2.x += x2*w.x; a2.y += x2*w.y; a2.z += x2*w.z; a2.w += x2*w.w;
            a3.x += x3*w.x; a3.y += x3*w.y; a3.z += x3*w.z; a3.w += x3*w.w;
        }
        if (EPI){
            float4 b = ((const float4*)bias)[cg];
            a0.x = fmaxf(a0.x+b.x, 0.f); a0.y = fmaxf(a0.y+b.y, 0.f);
            a0.z = fmaxf(a0.z+b.z, 0.f); a0.w = fmaxf(a0.w+b.w, 0.f);
            a1.x = fmaxf(a1.x+b.x, 0.f); a1.y = fmaxf(a1.y+b.y, 0.f);
            a1.z = fmaxf(a1.z+b.z, 0.f); a1.w = fmaxf(a1.w+b.w, 0.f);
            a2.x = fmaxf(a2.x+b.x, 0.f); a2.y = fmaxf(a2.y+b.y, 0.f);
            a2.z = fmaxf(a2.z+b.z, 0.f); a2.w = fmaxf(a2.w+b.w, 0.f);
            a3.x = fmaxf(a3.x+b.x, 0.f); a3.y = fmaxf(a3.y+b.y, 0.f);
            a3.z = fmaxf(a3.z+b.z, 0.f); a3.w = fmaxf(a3.w+b.w, 0.f);
        }
        float4* yp = (float4*)Y;
        int gr = row0 + r0;
        if (gr+0 < M) yp[(size_t)(gr+0)*CG + cg] = a0;
        if (gr+1 < M) yp[(size_t)(gr+1)*CG + cg] = a1;
        if (gr+2 < M) yp[(size_t)(gr+2)*CG + cg] = a2;
        if (gr+3 < M) yp[(size_t)(gr+3)*CG + cg] = a3;
    }
}

// ---------------- degree histogram ----------------
__global__ void deg_kernel(const int* __restrict__ dst, int* __restrict__ deg){
    int e = blockIdx.x*blockDim.x + threadIdx.x;
    if (e < DE) atomicAdd(&deg[dst[e]], 1);
}

// ---------------- 2-launch device-wide scan (bscan folded into scanwrite) ---
__global__ void blocksum_kernel(const int* __restrict__ deg, int* __restrict__ bsums, int M){
    __shared__ int sh[256];
    int tid = threadIdx.x;
    int base = blockIdx.x * 1024;
    int s = 0;
    #pragma unroll
    for (int j = 0; j < 4; j++){
        int i = base + tid + j*256;
        if (i < M) s += deg[i];
    }
    sh[tid] = s;
    __syncthreads();
    for (int o = 128; o; o >>= 1){
        if (tid < o) sh[tid] += sh[tid + o];
        __syncthreads();
    }
    if (tid == 0) bsums[blockIdx.x] = sh[0];
}

__global__ void scanwrite_kernel(const int* __restrict__ deg, const int* __restrict__ bsums,
                                 int* __restrict__ rowptr, int* __restrict__ cur,
                                 float* __restrict__ dis, int M){
    __shared__ int sh[1024];
    __shared__ int base_s;
    int tid = threadIdx.x;
    int i = blockIdx.x*1024 + tid;
    if (tid == 0){
        int a = 0;
        for (int j = 0; j < blockIdx.x; j++) a += bsums[j];
        base_s = a;
    }
    int v = (i < M) ? deg[i] : 0;
    sh[tid] = v;
    __syncthreads();
    #pragma unroll
    for (int o = 1; o < 1024; o <<= 1){
        int t = (tid >= o) ? sh[tid - o] : 0;
        __syncthreads();
        sh[tid] += t;
        __syncthreads();
    }
    if (i < M){
        int excl = base_s + sh[tid] - v;
        rowptr[i] = excl;
        cur[i]    = excl;
        dis[i]    = rsqrtf(1.0f + (float)v);
        if (i == M-1) rowptr[M] = excl + v;
    }
}

// ---------------- CSR scatter ----------------
__global__ void scatter1_kernel(const int* __restrict__ src, const int* __restrict__ dst,
                                int* __restrict__ cur, int* __restrict__ csr){
    int e = blockIdx.x*blockDim.x + threadIdx.x;
    if (e >= DE) return;
    int pos = atomicAdd(&cur[dst[e]], 1);
    csr[pos] = src[e];
}

__global__ void scatter2_kernel(const int* __restrict__ ns, const int* __restrict__ nd,
                                int* __restrict__ cur, int* __restrict__ csr){
    int e = blockIdx.x*blockDim.x + threadIdx.x;
    if (e >= DE) return;
    int a = ns[e];
    if (a < 0) return;
    int pos = atomicAdd(&cur[nd[e]], 1);
    csr[pos] = a;
}

// ---------------- 64-dim CSR gathers (warp per node, float2 lanes) ----------
// RAW: out = dis[n]^2 * H[n] + sum_{s in N(n)} dis[s]*dis[n]*H[s]   (no bias/relu)
__global__ void gather64_raw_kernel(const int* __restrict__ rowptr, const int* __restrict__ csr,
                                    const float* __restrict__ dis, const float* __restrict__ Hin,
                                    float* __restrict__ Hout, int M){
    int w = (blockIdx.x*blockDim.x + threadIdx.x) >> 5;
    int lane = threadIdx.x & 31;
    if (w >= M) return;
    int beg = rowptr[w], end = rowptr[w+1];
    float dn = dis[w];
    float2 h = ((const float2*)Hin)[(size_t)w*32 + lane];
    float s2 = dn*dn;
    float2 acc = make_float2(h.x*s2, h.y*s2);
    for (int j = beg; j < end; j++){
        int s = csr[j];
        float c = dis[s] * dn;
        float2 v = ((const float2*)Hin)[(size_t)s*32 + lane];
        acc.x += c*v.x; acc.y += c*v.y;
    }
    ((float2*)Hout)[(size_t)w*32 + lane] = acc;
}

// EPI: out = relu(raw + b)  (conv2)
__global__ void gather64_epi_kernel(const int* __restrict__ rowptr, const int* __restrict__ csr,
                                    const float* __restrict__ dis, const float* __restrict__ Hin,
                                    const float* __restrict__ bias, float* __restrict__ Hout, int M){
    int w = (blockIdx.x*blockDim.x + threadIdx.x) >> 5;
    int lane = threadIdx.x & 31;
    if (w >= M) return;
    int beg = rowptr[w], end = rowptr[w+1];
    float dn = dis[w];
    float2 h = ((const float2*)Hin)[(size_t)w*32 + lane];
    float s2 = dn*dn;
    float2 acc = make_float2(h.x*s2, h.y*s2);
    for (int j = beg; j < end; j++){
        int s = csr[j];
        float c = dis[s] * dn;
        float2 v = ((const float2*)Hin)[(size_t)s*32 + lane];
        acc.x += c*v.x; acc.y += c*v.y;
    }
    float2 b = ((const float2*)bias)[lane];
    acc.x = fmaxf(acc.x + b.x, 0.f);
    acc.y = fmaxf(acc.y + b.y, 0.f);
    ((float2*)Hout)[(size_t)w*32 + lane] = acc;
}

// conv4 gather fused with the global mean accumulation (bias at writeout)
__global__ void gather64_reduce_kernel(const int* __restrict__ rowptr, const int* __restrict__ csr,
                                       const float* __restrict__ dis, const float* __restrict__ Hin,
                                       float* __restrict__ accOut){
    __shared__ float sh[64];
    const int lane = threadIdx.x & 31;
    const int wloc = threadIdx.x >> 5;
    const int wpb  = blockDim.x >> 5;
    if (threadIdx.x < 64) sh[threadIdx.x] = 0.f;
    __syncthreads();
    int w = blockIdx.x*wpb + wloc;
    int tw = gridDim.x*wpb;
    float2 sum = make_float2(0.f, 0.f);
    for (int n = w; n < DK; n += tw){
        int beg = rowptr[n], end = rowptr[n+1];
        float dn = dis[n];
        float2 h = ((const float2*)Hin)[(size_t)n*32 + lane];
        float s2 = dn*dn;
        float2 a = make_float2(h.x*s2, h.y*s2);
        for (int j = beg; j < end; j++){
            int s = csr[j];
            float c = dis[s] * dn;
            float2 v = ((const float2*)Hin)[(size_t)s*32 + lane];
            a.x += c*v.x; a.y += c*v.y;
        }
        sum.x += a.x; sum.y += a.y;
    }
    atomicAdd(&sh[2*lane],   sum.x);
    atomicAdd(&sh[2*lane+1], sum.y);
    __syncthreads();
    if (threadIdx.x < 64) atomicAdd(&accOut[threadIdx.x], sh[threadIdx.x]);
}

__global__ void write_out_kernel(const float* __restrict__ acc, const float* __restrict__ b4,
                                 float* __restrict__ out){
    if (threadIdx.x < 64)
        out[threadIdx.x] = acc[threadIdx.x] * (1.0f/(float)DK) + b4[threadIdx.x];
}

// ---------------- pooling: score (wnorm folded in) + radix select -----------
__global__ void score_kernel(const float* __restrict__ H, const float* __restrict__ w,
                             float* __restrict__ score, u64* __restrict__ key){
    __shared__ float swn;
    __shared__ float red[8];
    int tid = threadIdx.x;
    // block-local ||w|| (128-dim)
    float q = (tid < 128) ? w[tid]*w[tid] : 0.f;
    #pragma unroll
    for (int o = 16; o; o >>= 1) q += __shfl_xor_sync(0xffffffffu, q, o);
    if ((tid & 31) == 0) red[tid >> 5] = q;
    __syncthreads();
    if (tid == 0) swn = sqrtf(red[0] + red[1] + red[2] + red[3]);
    __syncthreads();
    float wn = swn;

    int t = blockIdx.x*blockDim.x + tid;
    int n = t >> 5, lane = t & 31;
    if (n >= DN) return;
    float4 a = ((const float4*)H)[(size_t)n*32 + lane];
    float4 b = ((const float4*)w)[lane];
    float s = a.x*b.x + a.y*b.y + a.z*b.z + a.w*b.w;
    #pragma unroll
    for (int o = 16; o; o >>= 1) s += __shfl_xor_sync(0xffffffffu, s, o);
    if (lane == 0){
        s = tanhf(s / wn);
        score[n] = s;
        unsigned ub = __float_as_uint(s);
        ub = (ub & 0x80000000u) ? ~ub : (ub | 0x80000000u);   // order-preserving map
        key[n] = ((u64)ub << 32) | (u64)(0xffffffffu - (unsigned)n);  // distinct keys
    }
}

// histogram over the top byte of all keys
__global__ void hist_kernel(const u64* __restrict__ key, int* __restrict__ bins){
    __shared__ int sb[256];
    if (threadIdx.x < 256) sb[threadIdx.x] = 0;
    __syncthreads();
    for (int n = blockIdx.x*blockDim.x + threadIdx.x; n < DN; n += gridDim.x*blockDim.x)
        atomicAdd(&sb[(int)(key[n] >> 56)], 1);
    __syncthreads();
    if (threadIdx.x < 256 && sb[threadIdx.x]) atomicAdd(&bins[threadIdx.x], sb[threadIdx.x]);
}

// collect keys in the boundary bin (boundary byte derived from bins in-block)
__global__ void compact_kernel(const u64* __restrict__ key, const int* __restrict__ bins,
                               u64* __restrict__ cand, int* __restrict__ cnt){
    __shared__ int s_top;
    if (threadIdx.x == 0){
        int rem = DK;
        int bb = 0;
        for (int b = 255; b >= 0; b--){
            int c = bins[b];
            if (rem <= c){ bb = b; break; }
            rem -= c;
        }
        s_top = bb;
    }
    __syncthreads();
    u64 top = (u64)s_top;
    int n = blockIdx.x*blockDim.x + threadIdx.x;
    if (n >= DN) return;
    u64 k = key[n];
    if ((k >> 56) == top){
        int p = atomicAdd(cnt, 1);
        cand[p] = k;
    }
}

// remaining 7 radix passes in one block over the few candidates
__global__ void finish_select_kernel(const u64* __restrict__ cand, const int* __restrict__ cntp,
                                     const int* __restrict__ gbins, u64* __restrict__ pfxp){
    __shared__ int bins[256];
    __shared__ u64 s_pfx;
    __shared__ int s_rem;
    const int tid = threadIdx.x;
    const int C = *cntp;
    if (tid == 0){
        int rem = DK;
        int bb = 0;
        for (int b = 255; b >= 0; b--){
            int c = gbins[b];
            if (rem <= c){ bb = b; break; }
            rem -= c;
        }
        s_pfx = ((u64)bb) << 56;
        s_rem = rem;
    }
    __syncthreads();
    for (int shift = 48; shift >= 0; shift -= 8){
        if (tid < 256) bins[tid] = 0;
        __syncthreads();
        u64 pfx = s_pfx;
        for (int i = tid; i < C; i += blockDim.x){
            u64 k = cand[i];
            if ((k >> (shift+8)) == (pfx >> (shift+8)))
                atomicAdd(&bins[(int)((k >> shift) & 0xFF)], 1);
        }
        __syncthreads();
        if (tid == 0){
            int rem = s_rem;
            for (int b = 255; b >= 0; b--){
                int c = bins[b];
                if (rem <= c){ s_pfx = pfx | (((u64)b) << shift); break; }
                rem -= c;
            }
            s_rem = rem;
        }
        __syncthreads();
    }
    if (tid == 0) *pfxp = s_pfx;
}

// ---------------- compaction: new_idx for kept nodes ----------------
__global__ void count_kept_kernel(const u64* __restrict__ key, const u64* __restrict__ pfxp,
                                  int* __restrict__ bsum){
    __shared__ int sh[256];
    u64 pfx = *pfxp;
    int tid = threadIdx.x;
    int base = blockIdx.x*1024 + tid*4;
    int c = 0;
    #pragma unroll
    for (int j = 0; j < 4; j++){
        int n = base + j;
        if (n < DN && key[n] >= pfx) c++;
    }
    sh[tid] = c;
    __syncthreads();
    for (int s = 128; s; s >>= 1){
        if (tid < s) sh[tid] += sh[tid + s];
        __syncthreads();
    }
    if (tid == 0) bsum[blockIdx.x] = sh[0];
}

__global__ void newidx_kernel(const u64* __restrict__ key, const u64* __restrict__ pfxp,
                              const int* __restrict__ bsum, int* __restrict__ newidx){
    __shared__ int sh[256];
    __shared__ int s_base;
    u64 pfx = *pfxp;
    int tid = threadIdx.x;
    if (tid == 0){
        int a = 0;
        for (int j = 0; j < blockIdx.x; j++) a += bsum[j];
        s_base = a;
    }
    int base = blockIdx.x*1024 + tid*4;
    int kept[4]; int cnt = 0;
    #pragma unroll
    for (int j = 0; j < 4; j++){
        int n = base + j;
        kept[j] = (n < DN && key[n] >= pfx) ? 1 : 0;
        cnt += kept[j];
    }
    sh[tid] = cnt;
    __syncthreads();
    for (int s = 1; s < 256; s <<= 1){
        int v = (tid >= s) ? sh[tid - s] : 0;
        __syncthreads();
        sh[tid] += v;
        __syncthreads();
    }
    int off = s_base + sh[tid] - cnt;   // exclusive prefix
    #pragma unroll
    for (int j = 0; j < 4; j++){
        int n = base + j;
        if (n < DN) newidx[n] = kept[j] ? off++ : -1;
    }
}

__global__ void build_hp_kernel(const float* __restrict__ H, const int* __restrict__ newidx,
                                const float* __restrict__ score, float* __restrict__ HP){
    int i = blockIdx.x*blockDim.x + threadIdx.x;
    if (i >= DN*32) return;
    int n = i >> 5;
    int ni = newidx[n];
    if (ni < 0) return;
    float s = score[n];
    float4 v = ((const float4*)H)[i];
    v.x *= s; v.y *= s; v.z *= s; v.w *= s;
    ((float4*)HP)[(size_t)ni*32 + (i & 31)] = v;
}

__global__ void remap_kernel(const int* __restrict__ src, const int* __restrict__ dst,
                             const int* __restrict__ newidx,
                             int* __restrict__ ns, int* __restrict__ nd, int* __restrict__ deg){
    int e = blockIdx.x*blockDim.x + threadIdx.x;
    if (e >= DE) return;
    int a = newidx[src[e]];
    int b = newidx[dst[e]];
    if (a >= 0 && b >= 0){
        ns[e] = a; nd[e] = b;
        atomicAdd(&deg[b], 1);
    } else { ns[e] = -1; nd[e] = -1; }
}

// ---------------- launch ----------------
extern "C" void kernel_launch(void* const* d_in, const int* in_sizes, int n_in,
                              void* d_out, int out_size){
    const float* x   = (const float*)d_in[0];
    const int*   ei  = (const int*)  d_in[1];
    const int*   src = ei;
    const int*   dst = ei + DE;
    const float* W1  = (const float*)d_in[3];
    const float* b1  = (const float*)d_in[4];
    const float* pw  = (const float*)d_in[5];
    const float* W2  = (const float*)d_in[6];
    const float* b2  = (const float*)d_in[7];
    const float* W3  = (const float*)d_in[8];
    const float* b3  = (const float*)d_in[9];
    const float* W4  = (const float*)d_in[10];
    const float* b4  = (const float*)d_in[11];
    float* out = (float*)d_out;

    void* basep = nullptr;
    cudaGetSymbolAddress(&basep, g_scratch);
    unsigned char* B = (unsigned char*)basep;
    float* xa    = (float*)(B + OFF_XA);
    float* ha    = (float*)(B + OFF_HA);
    float* hp    = (float*)(B + OFF_HP);
    float* gm    = (float*)(B + OFF_GM);
    float* t2    = (float*)(B + OFF_T2);
    float* dis1  = (float*)(B + OFF_DIS1);
    float* dis2  = (float*)(B + OFF_DIS2);
    int*   deg1  = (int*)  (B + OFF_DEG1);
    int*   deg2  = (int*)  (B + OFF_DEG2);
    int*   rp1   = (int*)  (B + OFF_RP1);
    int*   cur1  = (int*)  (B + OFF_CUR1);
    int*   rp2   = (int*)  (B + OFF_RP2);
    int*   cur2  = (int*)  (B + OFF_CUR2);
    int*   csr1  = (int*)  (B + OFF_CSR1);
    int*   csr2  = (int*)  (B + OFF_CSR2);
    int*   ns    = (int*)  (B + OFF_NS);
    int*   nd    = (int*)  (B + OFF_ND);
    float* score = (float*)(B + OFF_SCORE);
    u64*   key   = (u64*)  (B + OFF_KEY);
    u64*   cand  = (u64*)  (B + OFF_CAND);
    int*   nidx  = (int*)  (B + OFF_NEW);
    int*   bins  = (int*)  (B + OFF_BINS);
    int*   bsum  = (int*)  (B + OFF_BSUM);
    u64*   pfx   = (u64*)  (B + OFF_PFX);
    int*   ccnt  = (int*)  (B + OFF_CCNT);
    float* acc   = (float*)(B + OFF_ACC);

    const int T = 256;
    const int NB1 = (DN + 1023)/1024;   // 49
    const int NB2 = (DK + 1023)/1024;   // 40
    const int SMEM_G1 = (64*128 + 64*64)*4;    // 48 KB (KIN=64, KOUT=128, ROWS=64)
    const int SMEM_G2 = (128*64 + 64*128)*4;   // 64 KB (KIN=128, KOUT=64, ROWS=64)
    cudaFuncSetAttribute(gemm_rt<128,64,64,false>, cudaFuncAttributeMaxDynamicSharedMemorySize, SMEM_G2);

    // reset all per-replay state
    init_kernel<<<(DN+T-1)/T, T>>>(deg1, deg2, bins, acc, ccnt);

    // ---- CSR for the full graph ----
    deg_kernel<<<(DE+T-1)/T, T>>>(dst, deg1);
    blocksum_kernel<<<NB1, 256>>>(deg1, bsum, DN);
    scanwrite_kernel<<<NB1, 1024>>>(deg1, bsum, rp1, cur1, dis1, DN);
    scatter1_kernel<<<(DE+T-1)/T, T>>>(src, dst, cur1, csr1);

    // ---- conv1: gather in 64-dim INPUT space, then GEMM(+bias+relu) ----
    gather64_raw_kernel<<<(DN*32+T-1)/T, T>>>(rp1, csr1, dis1, x, xa, DN);
    gemm_rt<64,128,64,true><<<(DN+63)/64, T, SMEM_G1>>>(xa, W1, b1, ha, DN);

    // ---- TopK pooling (exact radix select) ----
    score_kernel<<<(DN*32+T-1)/T, T>>>(ha, pw, score, key);
    hist_kernel<<<128, T>>>(key, bins);
    compact_kernel<<<(DN+T-1)/T, T>>>(key, bins, cand, ccnt);
    finish_select_kernel<<<1, 1024>>>(cand, ccnt, bins, pfx);
    count_kept_kernel<<<NBLK, T>>>(key, pfx, bsum);
    newidx_kernel<<<NBLK, T>>>(key, pfx, bsum, nidx);
    build_hp_kernel<<<(DN*32+T-1)/T, T>>>(ha, nidx, score, hp);
    remap_kernel<<<(DE+T-1)/T, T>>>(src, dst, nidx, ns, nd, deg2);
    blocksum_kernel<<<NB2, 256>>>(deg2, bsum, DK);
    scanwrite_kernel<<<NB2, 1024>>>(deg2, bsum, rp2, cur2, dis2, DK);
    scatter2_kernel<<<(DE+T-1)/T, T>>>(ns, nd, cur2, csr2);

    // ---- conv2 (128 -> 64): GEMM first, gather in 64-dim + bias + relu ----
    gemm_rt<128,64,64,false><<<(DK+63)/64, T, SMEM_G2>>>(hp, W2, nullptr, gm, DK);
    gather64_epi_kernel<<<(DK*32+T-1)/T, T>>>(rp2, csr2, dis2, gm, b2, t2, DK);

    // ---- conv3 (64 -> 128): gather in 64-dim INPUT space, then GEMM epi ----
    gather64_raw_kernel<<<(DK*32+T-1)/T, T>>>(rp2, csr2, dis2, t2, xa, DK);
    gemm_rt<64,128,64,true><<<(DK+63)/64, T, SMEM_G1>>>(xa, W3, b3, ha, DK);

    // ---- conv4 (128 -> 64): GEMM first, gather fused with global mean ----
    gemm_rt<128,64,64,false><<<(DK+63)/64, T, SMEM_G2>>>(ha, W4, nullptr, gm, DK);
    gather64_reduce_kernel<<<296, T>>>(rp2, csr2, dis2, gm, acc);
    write_out_kernel<<<1,64>>>(acc, b4, out);
}